// round 8
// baseline (speedup 1.0000x reference)
#include <cuda_runtime.h>

#define NQ 9
#define HOUT 128
#define WOUT 128
#define HW 384
#define PLANE (HOUT * WOUT)

// 1 thread = 2 adjacent 3x3 windows (columns 6w..6w+5 of 3 rows).
// All loads are LDG.64 (8B-aligned), all stores STG.64 (one per plane).
// Warp-autonomous setup: z = R_q * sin(pi*x + phi_q), constants built with
// __sincosf + shuffles, hidden under the in-flight pixel loads.
__global__ void __launch_bounds__(256) quanconv_fused2(
    const float* __restrict__ in, const float* __restrict__ w,
    float* __restrict__ out) {

    const unsigned FULL = 0xFFFFFFFFu;
    const int tid  = threadIdx.x;
    const int lane = tid & 31;
    const int gid  = blockIdx.x * 256 + tid;    // 0..32767 window-pairs
    const int wp = gid & (WOUT / 2 - 1);        // 0..63
    const int ho = (gid >> 6) & (HOUT - 1);
    const int b  = gid >> 13;

    // ---- weight load first ----
    const float M = 0.63245553203367586640f;    // sqrt(2/5) = W_MUL
    float ww = __ldg(w + (lane < 27 ? lane : 26)) * M;

    // ---- issue 9 x LDG.64 (3 rows x 3 float2), all independent ----
    const float2* base2 = (const float2*)(in + (b * HW + ho * 3) * HW) + 3 * wp;
    float2 r0a = __ldg(base2 + 0), r0b = __ldg(base2 + 1), r0c = __ldg(base2 + 2);
    const float2* row1 = base2 + HW / 2;
    float2 r1a = __ldg(row1 + 0), r1b = __ldg(row1 + 1), r1c = __ldg(row1 + 2);
    const float2* row2 = base2 + HW;
    float2 r2a = __ldg(row2 + 0), r2b = __ldg(row2 + 1), r2c = __ldg(row2 + 2);

    // ---- per-warp setup (overlaps loads) ----
    float s, c;
    __sincosf(ww, &s, &c);
    float s0 = __shfl_sync(FULL, s, 3 * lane);
    float c0 = __shfl_sync(FULL, c, 3 * lane);
    float s1 = __shfl_sync(FULL, s, 3 * lane + 1);
    float c1 = __shfl_sync(FULL, c, 3 * lane + 1);
    float s2 = __shfl_sync(FULL, s, 3 * lane + 2);
    float c2 = __shfl_sync(FULL, c, 3 * lane + 2);
    float A = s1 * s2;
    float B = fmaf(c0, c2, -(s0 * c1 * s2));
    float Rv  = sqrtf(fmaf(A, A, B * B));
    float Phi = atan2f(B, A);                   // lanes 0..8 meaningful

    float Rq[NQ], Pq[NQ];
#pragma unroll
    for (int q = 0; q < NQ; q++) {
        Rq[q] = __shfl_sync(FULL, Rv,  q);
        Pq[q] = __shfl_sync(FULL, Phi, q);
    }

    // window 0 pixels: r0a.x r0a.y r0b.x / r1a.x r1a.y r1b.x / r2a.x r2a.y r2b.x
    // window 1 pixels: r0b.y r0c.x r0c.y / r1b.y r1c.x r1c.y / r2b.y r2c.x r2c.y
    float xa[NQ] = { r0a.x, r0a.y, r0b.x, r1a.x, r1a.y, r1b.x, r2a.x, r2a.y, r2b.x };
    float xb[NQ] = { r0b.y, r0c.x, r0c.y, r1b.y, r1c.x, r1c.y, r2b.y, r2c.x, r2c.y };

    const float PI_F = 3.14159274101257324219f;
    float za[NQ], zb[NQ];
#pragma unroll
    for (int q = 0; q < NQ; q++) {
        za[q] = Rq[q] * __sinf(fmaf(PI_F, xa[q], Pq[q]));
        zb[q] = Rq[q] * __sinf(fmaf(PI_F, xb[q], Pq[q]));
    }

    // outputs: plane j>=1 = prod z0..zj ; plane 0 = prod z1..z8
    float2 o[NQ];
    float pa = za[0], pb = zb[0];
#pragma unroll
    for (int j = 1; j < NQ; j++) {
        pa *= za[j];
        pb *= zb[j];
        o[j].x = pa; o[j].y = pb;
    }
    // suffix z1..z8 via tree (independent chains)
    float sa = (za[1] * za[2]) * (za[3] * za[4]);
    sa *= (za[5] * za[6]) * (za[7] * za[8]);
    float sb = (zb[1] * zb[2]) * (zb[3] * zb[4]);
    sb *= (zb[5] * zb[6]) * (zb[7] * zb[8]);
    o[0].x = sa; o[0].y = sb;

    float2* obase = (float2*)(out + b * (NQ * PLANE) + ho * WOUT) + wp;
#pragma unroll
    for (int j = 0; j < NQ; j++)
        obase[j * (PLANE / 2)] = o[j];
}

extern "C" void kernel_launch(void* const* d_in, const int* in_sizes, int n_in,
                              void* d_out, int out_size) {
    const float* x = (const float*)d_in[0];   // (4,1,384,384) float32
    const float* w = (const float*)d_in[1];   // (27,) float32
    float* out = (float*)d_out;               // (4,9,128,128) float32

    quanconv_fused2<<<32768 / 256, 256>>>(x, w, out);
}